// round 6
// baseline (speedup 1.0000x reference)
#include <cuda_runtime.h>
#include <cuda_fp16.h>
#include <cstdint>

// ---------------------------------------------------------------------------
// VectorQuantize: two-pass fp16 hi-only prefilter GEMM (mma.sync.m16n8k16,
// f32 accum) + margin-based exact fp32 rescore.
//  Pass A: rowmax of approx scores.  Pass B: candidates > rowmax-0.25 ->
//  exact fp32 rescore, argmax with lowest-index tie-break.
// ---------------------------------------------------------------------------

#define NCODES 8192
#define OFF_Q     0
#define OFF_IND   2097152
#define OFF_LOSS  2129920
#define OFF_NC    2129921
#define OFF_EA    2138113
#define OFF_NE    2662401
#define OUT_FULL  3186689

#define RPB      128
#define NTILES   64
#define DELTA    0.25f
#define CAND_MAX 2048

// smem word offsets (floats)
#define W_A    0        // A2: uint2[2048] = [4 kc16][128 row][4 kl]
#define W_B    4096     // 2 stages x uint2[2048]
#define W_CN   12288    // 2 x 128
#define W_TH   12544    // 128 thresholds
#define W_RED  12672    // 2 halves x 128 rowmax
#define W_RB   12928    // u64 rowbest[128] (256 words, 8B aligned)
#define W_IND  13184    // 128 ints
#define W_LIST 13312    // 2048 candidate codes
#define W_CNT  15360
#define W_LOSS 15361
#define SMEM_TOTAL 61448

// device scratch
__device__ float g_pe[65536];
__device__ __align__(16) float g_cn[NCODES];
__device__ float g_counts[NCODES];
__device__ float g_esum[64 * NCODES];
__device__ __align__(16) float g_et[NCODES * 64];   // E^T fp32 [j][k]
__device__ __align__(16) uint4 g_eb[NCODES * 8];    // E^T fp16-hi frag chunks
__device__ float g_loss, g_total;

// ---------------------------------------------------------------------------
__device__ __forceinline__ uint32_t smem_u32(const void* p) {
    uint32_t a;
    asm("{ .reg .u64 t; cvta.to.shared.u64 t, %1; cvt.u32.u64 %0, t; }"
        : "=r"(a) : "l"(p));
    return a;
}
__device__ __forceinline__ void mma16(float* d, uint32_t a0, uint32_t a1,
                                      uint32_t a2, uint32_t a3,
                                      uint32_t b0, uint32_t b1) {
    asm volatile(
        "mma.sync.aligned.m16n8k16.row.col.f32.f16.f16.f32 "
        "{%0,%1,%2,%3}, {%4,%5,%6,%7}, {%8,%9}, {%0,%1,%2,%3};"
        : "+f"(d[0]), "+f"(d[1]), "+f"(d[2]), "+f"(d[3])
        : "r"(a0), "r"(a1), "r"(a2), "r"(a3), "r"(b0), "r"(b1));
}
__device__ __forceinline__ void cp16(uint32_t dst, const void* src) {
    asm volatile("cp.async.cg.shared.global [%0], [%1], 16;"
                 :: "r"(dst), "l"(src) : "memory");
}
#define CP_COMMIT() asm volatile("cp.async.commit_group;" ::: "memory")
#define CP_WAIT1()  asm volatile("cp.async.wait_group 1;" ::: "memory")
#define CP_WAIT0()  asm volatile("cp.async.wait_group 0;" ::: "memory")

__device__ __forceinline__ uint32_t pkh(float a, float b) {
    __half2 h = __floats2half2_rn(a, b);
    return *(uint32_t*)&h;
}

// ---------------------------------------------------------------------------
// prep0: PE table, zero scratch.  grid 2048 x 256
// ---------------------------------------------------------------------------
__global__ void vq_prep0(const float* __restrict__ pos_emb) {
    int idx = blockIdx.x * 256 + threadIdx.x;
    g_esum[idx] = 0.0f;
    if (idx < 65536) {
        int jj = idx & 63, i = (idx >> 6) & 63, c = idx >> 12;
        int s = ((i >> 2) << 4) + (jj >> 2);
        int d = (c << 4) + ((i & 3) << 2) + (jj & 3);
        g_pe[idx] = pos_emb[s * 256 + d];
    }
    if (idx < NCODES) g_counts[idx] = 0.0f;
    if (idx == 0) { g_loss = 0.0f; g_total = 0.0f; }
}

// ---------------------------------------------------------------------------
// prep1: transpose embed -> g_et, fp16-hi fragment chunks, code norms.
// grid 64 x 256 (block = 128 codes).
// ---------------------------------------------------------------------------
__global__ void vq_prep1(const float* __restrict__ embed) {
    __shared__ float sE[64][129];
    __shared__ float scn[128][2];
    const int tid = threadIdx.x;
    const int j0 = blockIdx.x * 128;
#pragma unroll 4
    for (int kk = 0; kk < 32; kk++) {
        int k = kk * 2 + (tid >> 7);
        int jl = tid & 127;
        sE[k][jl] = embed[(size_t)k * NCODES + j0 + jl];
    }
    __syncthreads();
    const int jl = tid & 127, kh = tid >> 7;
    const int j = j0 + jl;
    float ssum = 0.0f;
#pragma unroll
    for (int kc = 2 * kh; kc <= 2 * kh + 1; kc++) {
        float v[16];
        uint32_t w1[4], w2[4];
#pragma unroll
        for (int q = 0; q < 16; q++) {
            v[q] = sE[kc * 16 + q][jl];
            ssum += v[q] * v[q];
        }
#pragma unroll
        for (int q = 0; q < 8; q++)
            *(float2*)(g_et + (size_t)j * 64 + kc * 16 + 2 * q) =
                make_float2(v[2 * q], v[2 * q + 1]);
#pragma unroll
        for (int kl = 0; kl < 4; kl++) {
            w1[kl] = pkh(v[2 * kl], v[2 * kl + 1]);
            w2[kl] = pkh(v[2 * kl + 8], v[2 * kl + 9]);
        }
#pragma unroll
        for (int kp = 0; kp < 2; kp++)
            g_eb[(size_t)j * 8 + kc * 2 + kp] =
                make_uint4(w1[2 * kp], w2[2 * kp], w1[2 * kp + 1], w2[2 * kp + 1]);
    }
    scn[jl][kh] = ssum;
    __syncthreads();
    if (tid < 128) g_cn[j0 + tid] = -0.5f * (scn[tid][0] + scn[tid][1]);
}

// ---------------------------------------------------------------------------
// async B tile: g_eb -> smem [kc16][col][kl] uint2 (1:1 16B chunks)
// ---------------------------------------------------------------------------
__device__ __forceinline__ void load_b_tile(uint32_t smem_base, int t, int tid) {
    const int cb = t * 128;
    const uint32_t bb = smem_base + (uint32_t)(W_B + (t & 1) * 4096) * 4u;
#pragma unroll
    for (int i = 0; i < 4; i++) {
        int c = tid + (i << 8);             // 0..1023 16B chunks
        int kc16 = c >> 8, col = (c >> 1) & 127, kp = c & 1;
        cp16(bb + (uint32_t)c * 16u, g_eb + (size_t)(cb + col) * 8 + kc16 * 2 + kp);
    }
    if (tid < 32)
        cp16(smem_base + (uint32_t)(W_CN + (t & 1) * 128) * 4u + tid * 16,
             g_cn + cb + tid * 4);
}

// ---------------------------------------------------------------------------
// main: 256 CTAs x 256 threads, 2 CTAs/SM.
// ---------------------------------------------------------------------------
__global__ void __launch_bounds__(256, 2)
vq_main(const float* __restrict__ input, float* __restrict__ out, int full) {
    extern __shared__ float smf[];
    const uint32_t smem_base = smem_u32(smf);
    const int tid = threadIdx.x, wid = tid >> 5, lane = tid & 31;
    const int wr = wid >> 1, wc = wid & 1;
    const int g = lane >> 2, kl = lane & 3;
    const int row0 = blockIdx.x * RPB;

    uint2* A2 = (uint2*)(smf + W_A);
    int* IndSh = (int*)(smf + W_IND);
    unsigned long long* RB = (unsigned long long*)(smf + W_RB);
    uint32_t* LIST = (uint32_t*)(smf + W_LIST);
    int* CNT = (int*)(smf + W_CNT);
    if (tid == 0) { smf[W_LOSS] = 0.0f; *CNT = 0; }

    // ---- A build: X = input + pe, fp16-hi fragment layout ----
    {
        int row = tid >> 1, h = tid & 1, rg = row0 + row;
        const float4* ip = (const float4*)(input + (size_t)rg * 64);
        const float4* pp = (const float4*)(g_pe + (size_t)(rg & 1023) * 64);
#pragma unroll
        for (int kc = 2 * h; kc <= 2 * h + 1; kc++) {
            float xv[16];
#pragma unroll
            for (int q = 0; q < 4; q++) {
                float4 a = ip[kc * 4 + q], b = pp[kc * 4 + q];
                xv[4 * q + 0] = a.x + b.x; xv[4 * q + 1] = a.y + b.y;
                xv[4 * q + 2] = a.z + b.z; xv[4 * q + 3] = a.w + b.w;
            }
#pragma unroll
            for (int klx = 0; klx < 4; klx++)
                A2[kc * 512 + row * 4 + klx] =
                    make_uint2(pkh(xv[2 * klx], xv[2 * klx + 1]),
                               pkh(xv[2 * klx + 8], xv[2 * klx + 9]));
        }
    }
    load_b_tile(smem_base, 0, tid); CP_COMMIT();
    load_b_tile(smem_base, 1, tid); CP_COMMIT();

    const int r0m0 = wr * 32 + g;

    // ================= PASS A: rowmax of approx scores =================
    float best[4];
#pragma unroll
    for (int s = 0; s < 4; s++) best[s] = -3.4e38f;

    for (int t = 0; t < NTILES; t++) {
        CP_WAIT1();
        __syncthreads();
        const uint2* B2 = (const uint2*)(smf + W_B + (t & 1) * 4096);
        const float* cn = smf + W_CN + (t & 1) * 128 + wc * 64;

        float acc[2][8][4];
#pragma unroll
        for (int nf = 0; nf < 8; nf++) {
            float c0 = cn[nf * 8 + 2 * kl], c1 = cn[nf * 8 + 2 * kl + 1];
#pragma unroll
            for (int m = 0; m < 2; m++) {
                acc[m][nf][0] = c0; acc[m][nf][1] = c1;
                acc[m][nf][2] = c0; acc[m][nf][3] = c1;
            }
        }
#pragma unroll
        for (int kc16 = 0; kc16 < 4; kc16++) {
            uint2 alo[2], ahi[2];
#pragma unroll
            for (int m = 0; m < 2; m++) {
                int r = r0m0 + m * 16;
                alo[m] = A2[kc16 * 512 + r * 4 + kl];
                ahi[m] = A2[kc16 * 512 + (r + 8) * 4 + kl];
            }
#pragma unroll
            for (int nf = 0; nf < 8; nf++) {
                uint2 b = B2[kc16 * 512 + (wc * 64 + nf * 8 + g) * 4 + kl];
#pragma unroll
                for (int m = 0; m < 2; m++)
                    mma16(acc[m][nf], alo[m].x, ahi[m].x, alo[m].y, ahi[m].y,
                          b.x, b.y);
            }
        }
#pragma unroll
        for (int m = 0; m < 2; m++)
#pragma unroll
            for (int nf = 0; nf < 8; nf++) {
                best[2 * m]     = fmaxf(best[2 * m],
                                        fmaxf(acc[m][nf][0], acc[m][nf][1]));
                best[2 * m + 1] = fmaxf(best[2 * m + 1],
                                        fmaxf(acc[m][nf][2], acc[m][nf][3]));
            }
        __syncthreads();
        if (t + 2 < NTILES) load_b_tile(smem_base, t + 2, tid);
        CP_COMMIT();
    }
    CP_WAIT0();

    // rowmax reduce: quad shuffle then smem
#pragma unroll
    for (int s = 0; s < 4; s++) {
        float v = best[s];
        v = fmaxf(v, __shfl_xor_sync(0xffffffffu, v, 1));
        v = fmaxf(v, __shfl_xor_sync(0xffffffffu, v, 2));
        if ((lane & 3) == 0) {
            int rowl = wr * 32 + (s >> 1) * 16 + (s & 1) * 8 + g;
            smf[W_RED + wc * 128 + rowl] = v;
        }
    }
    __syncthreads();
    if (tid < 128) {
        smf[W_TH + tid] = fmaxf(smf[W_RED + tid], smf[W_RED + 128 + tid]) - DELTA;
        RB[tid] = 0ULL;
    }
    __syncthreads();

    // ================= PASS B: candidates above threshold =================
    load_b_tile(smem_base, 0, tid); CP_COMMIT();
    load_b_tile(smem_base, 1, tid); CP_COMMIT();

    float th[4];
#pragma unroll
    for (int s = 0; s < 4; s++)
        th[s] = smf[W_TH + wr * 32 + (s >> 1) * 16 + (s & 1) * 8 + g];

    for (int t = 0; t < NTILES; t++) {
        CP_WAIT1();
        __syncthreads();
        const uint2* B2 = (const uint2*)(smf + W_B + (t & 1) * 4096);
        const float* cn = smf + W_CN + (t & 1) * 128 + wc * 64;

        float acc[2][8][4];
#pragma unroll
        for (int nf = 0; nf < 8; nf++) {
            float c0 = cn[nf * 8 + 2 * kl], c1 = cn[nf * 8 + 2 * kl + 1];
#pragma unroll
            for (int m = 0; m < 2; m++) {
                acc[m][nf][0] = c0; acc[m][nf][1] = c1;
                acc[m][nf][2] = c0; acc[m][nf][3] = c1;
            }
        }
#pragma unroll
        for (int kc16 = 0; kc16 < 4; kc16++) {
            uint2 alo[2], ahi[2];
#pragma unroll
            for (int m = 0; m < 2; m++) {
                int r = r0m0 + m * 16;
                alo[m] = A2[kc16 * 512 + r * 4 + kl];
                ahi[m] = A2[kc16 * 512 + (r + 8) * 4 + kl];
            }
#pragma unroll
            for (int nf = 0; nf < 8; nf++) {
                uint2 b = B2[kc16 * 512 + (wc * 64 + nf * 8 + g) * 4 + kl];
#pragma unroll
                for (int m = 0; m < 2; m++)
                    mma16(acc[m][nf], alo[m].x, ahi[m].x, alo[m].y, ahi[m].y,
                          b.x, b.y);
            }
        }
        int colb = t * 128 + wc * 64 + 2 * kl;
#pragma unroll
        for (int m = 0; m < 2; m++) {
            int ra = wr * 32 + m * 16 + g, rb = ra + 8;
#pragma unroll
            for (int nf = 0; nf < 8; nf++) {
                int c01 = colb + nf * 8;
                if (acc[m][nf][0] > th[2 * m]) {
                    int p = atomicAdd(CNT, 1);
                    if (p < CAND_MAX) LIST[p] = (ra << 13) | c01;
                }
                if (acc[m][nf][1] > th[2 * m]) {
                    int p = atomicAdd(CNT, 1);
                    if (p < CAND_MAX) LIST[p] = (ra << 13) | (c01 + 1);
                }
                if (acc[m][nf][2] > th[2 * m + 1]) {
                    int p = atomicAdd(CNT, 1);
                    if (p < CAND_MAX) LIST[p] = (rb << 13) | c01;
                }
                if (acc[m][nf][3] > th[2 * m + 1]) {
                    int p = atomicAdd(CNT, 1);
                    if (p < CAND_MAX) LIST[p] = (rb << 13) | (c01 + 1);
                }
            }
        }
        __syncthreads();
        if (t + 2 < NTILES) load_b_tile(smem_base, t + 2, tid);
        CP_COMMIT();
    }
    CP_WAIT0();
    __syncthreads();

    // ---- exact fp32 rescore of candidates ----
    {
        int n = *CNT;
        n = n < CAND_MAX ? n : CAND_MAX;
        for (int i = tid; i < n; i += 256) {
            uint32_t e = LIST[i];
            int row = e >> 13, col = e & 8191;
            int rg = row0 + row;
            const float4* ip = (const float4*)(input + (size_t)rg * 64);
            const float4* pp = (const float4*)(g_pe + (size_t)(rg & 1023) * 64);
            const float4* ep = (const float4*)(g_et + (size_t)col * 64);
            float s = g_cn[col];
#pragma unroll
            for (int q = 0; q < 16; q++) {
                float4 a = ip[q], b = pp[q], ev = ep[q];
                s = fmaf(a.x + b.x, ev.x, s);
                s = fmaf(a.y + b.y, ev.y, s);
                s = fmaf(a.z + b.z, ev.z, s);
                s = fmaf(a.w + b.w, ev.w, s);
            }
            uint32_t ub = __float_as_uint(s);
            ub = (ub & 0x80000000u) ? ~ub : (ub | 0x80000000u);
            unsigned long long key =
                ((unsigned long long)ub << 32) | (uint32_t)(8191 - col);
            atomicMax(&RB[row], key);
        }
    }
    __syncthreads();

    if (tid < 128) {
        int bj = 8191 - (int)(RB[tid] & 0x1FFFu);
        IndSh[tid] = bj;
        if (full) out[OFF_IND + row0 + tid] = (float)bj;
        atomicAdd(&g_counts[bj], 1.0f);
    }
    __syncthreads();

    // ---- epilogue: quantize gather, loss, embed_sum scatter ----
    {
        float lsum = 0.0f;
        for (int it = 0; it < 16; it++) {
            int rloc = wid * 16 + it;
            int rg = row0 + rloc;
            int j = IndSh[rloc];
#pragma unroll
            for (int h2 = 0; h2 < 2; h2++) {
                int k = lane + 32 * h2;
                float ev = g_et[(size_t)j * 64 + k];
                float iv = input[(size_t)rg * 64 + k];
                float dd = ev - iv;
                lsum += dd * dd;
                out[OFF_Q + (size_t)rg * 64 + k] = ev;
                float xv2 = iv + g_pe[(rg & 1023) * 64 + k];
                atomicAdd(&g_esum[(size_t)k * NCODES + j], xv2);
            }
        }
#pragma unroll
        for (int off = 16; off; off >>= 1)
            lsum += __shfl_down_sync(0xffffffffu, lsum, off);
        if (lane == 0) atomicAdd(smf + W_LOSS, lsum);
    }
    __syncthreads();
    if (tid == 0) atomicAdd(&g_loss, smf[W_LOSS]);
}

// ---------------------------------------------------------------------------
__global__ void vq_fin1(const float* __restrict__ cs, float* __restrict__ out) {
    int j = blockIdx.x * 256 + threadIdx.x;
    float nc = 0.8f * cs[j] + 0.2f * g_counts[j];
    out[OFF_NC + j] = nc;
    __shared__ float sh[256];
    sh[threadIdx.x] = nc;
    __syncthreads();
    for (int s = 128; s; s >>= 1) {
        if (threadIdx.x < s) sh[threadIdx.x] += sh[threadIdx.x + s];
        __syncthreads();
    }
    if (threadIdx.x == 0) atomicAdd(&g_total, sh[0]);
}

__global__ void vq_fin2(const float* __restrict__ ea, float* __restrict__ out) {
    int idx = blockIdx.x * 256 + threadIdx.x;
    int j = idx & (NCODES - 1);
    float nea = 0.8f * ea[idx] + 0.2f * g_esum[idx];
    out[OFF_EA + idx] = nea;
    float total = g_total;
    float nc = out[OFF_NC + j];
    float smoothed = (nc + 1e-5f) / (total + NCODES * 1e-5f) * total;
    out[OFF_NE + idx] = nea / smoothed;
    if (idx == 0) out[OFF_LOSS] = g_loss * (1.0f / 2097152.0f);
}

// ---------------------------------------------------------------------------
extern "C" void kernel_launch(void* const* d_in, const int* in_sizes, int n_in,
                              void* d_out, int out_size) {
    const float* input = (const float*)d_in[0];
    const float* embed = (const float*)d_in[1];
    const float* pos   = (const float*)d_in[2];
    const float* cs    = (const float*)d_in[3];
    const float* ea    = (const float*)d_in[4];
    float* out = (float*)d_out;

    cudaFuncSetAttribute(vq_main, cudaFuncAttributeMaxDynamicSharedMemorySize,
                         SMEM_TOTAL);
    int full = (out_size >= OUT_FULL) ? 1 : 0;

    vq_prep0<<<2048, 256>>>(pos);
    vq_prep1<<<64, 256>>>(embed);
    vq_main<<<256, 256, SMEM_TOTAL>>>(input, out, full);
    if (full) {
        vq_fin1<<<NCODES / 256, 256>>>(cs, out);
        vq_fin2<<<(64 * NCODES) / 256, 256>>>(ea, out);
    }
}